// round 5
// baseline (speedup 1.0000x reference)
#include <cuda_runtime.h>
#include <cuda_fp16.h>
#include <cstdint>

// B=64, N=1000, D=512, H=8, S=20, DK=64
#define NEG_BIG (-1e9f)
#define INV_SQRT_DK 0.125f
#define INV_SQRT_D 0.04419417382415922f
#define EMB_SCALE 32.0f
#define W_SCALE 256.0f
#define DEQ_SCALE (1.0f / (32.0f * 256.0f))

// ---------------- device scratch ----------------
__device__ __align__(16) __half g_kvlh[64000 * 1536];    // fp16 [b*1000+n][gk|gv|lk]
__device__ __align__(16) float g_heads[1280 * 512];
__device__ __align__(16) float g_glimpse[1280 * 512];
__device__ __align__(16) float g_logits[1280 * 1000];
__device__ __align__(16) int8_t g_As8[64000 * 512];      // quantized embeddings
__device__ __align__(16) int8_t g_Wkvl_s8[1536 * 512];   // W_kvl^T quantized [n][k]
__device__ __align__(16) __half g_Wout_t[512 * 512];     // W_out^T fp16 [n][k]
__device__ __align__(16) __half g_Hf16[1280 * 512];
__device__ int g_mask_mode;

// ---------------- helpers ----------------
__device__ __forceinline__ bool is_feasible(const void* mp, int idx, int mode) {
    if (mode) return ((const unsigned int*)mp)[idx] != 0u;
    return ((const unsigned char*)mp)[idx] != 0;
}
__device__ __forceinline__ float warp_max(float v) {
#pragma unroll
    for (int o = 16; o; o >>= 1) v = fmaxf(v, __shfl_xor_sync(0xffffffffu, v, o));
    return v;
}
__device__ __forceinline__ float warp_sum(float v) {
#pragma unroll
    for (int o = 16; o; o >>= 1) v += __shfl_xor_sync(0xffffffffu, v, o);
    return v;
}
__device__ __forceinline__ uint32_t smem_u32(const void* p) {
    uint32_t a;
    asm("{ .reg .u64 t; cvta.to.shared.u64 t, %1; cvt.u32.u64 %0, t; }" : "=r"(a) : "l"(p));
    return a;
}
__device__ __forceinline__ void cp_async16(uint32_t saddr, const void* gaddr) {
    asm volatile("cp.async.cg.shared.global [%0], [%1], 16;" :: "r"(saddr), "l"(gaddr));
}
__device__ __forceinline__ void cp_commit() { asm volatile("cp.async.commit_group;" ::: "memory"); }
__device__ __forceinline__ void cp_wait1() { asm volatile("cp.async.wait_group 1;" ::: "memory"); }
__device__ __forceinline__ void cp_wait0() { asm volatile("cp.async.wait_group 0;" ::: "memory"); }

__device__ __forceinline__ void ldsm_x4(uint32_t& r0, uint32_t& r1, uint32_t& r2, uint32_t& r3,
                                        uint32_t addr) {
    asm volatile("ldmatrix.sync.aligned.m8n8.x4.shared.b16 {%0,%1,%2,%3}, [%4];"
                 : "=r"(r0), "=r"(r1), "=r"(r2), "=r"(r3) : "r"(addr));
}
// fp16 MMA (glimpse GEMM)
__device__ __forceinline__ void mma16816(float& c0, float& c1, float& c2, float& c3,
                                         uint32_t a0, uint32_t a1, uint32_t a2, uint32_t a3,
                                         uint32_t b0, uint32_t b1) {
    asm volatile(
        "mma.sync.aligned.m16n8k16.row.col.f32.f16.f16.f32 "
        "{%0,%1,%2,%3}, {%4,%5,%6,%7}, {%8,%9}, {%0,%1,%2,%3};"
        : "+f"(c0), "+f"(c1), "+f"(c2), "+f"(c3)
        : "r"(a0), "r"(a1), "r"(a2), "r"(a3), "r"(b0), "r"(b1));
}
// int8 MMA (kvl GEMM)
__device__ __forceinline__ void imma16832(int& c0, int& c1, int& c2, int& c3,
                                          uint32_t a0, uint32_t a1, uint32_t a2, uint32_t a3,
                                          uint32_t b0, uint32_t b1) {
    asm volatile(
        "mma.sync.aligned.m16n8k32.row.col.s32.s8.s8.s32 "
        "{%0,%1,%2,%3}, {%4,%5,%6,%7}, {%8,%9}, {%0,%1,%2,%3};"
        : "+r"(c0), "+r"(c1), "+r"(c2), "+r"(c3)
        : "r"(a0), "r"(a1), "r"(a2), "r"(a3), "r"(b0), "r"(b1));
}

// ---------------- mask dtype sniffer ----------------
__global__ void detect_mask_kernel(const unsigned int* mw) {
    __shared__ int notI32, notF32;
    if (threadIdx.x == 0) { notI32 = 0; notF32 = 0; }
    __syncthreads();
    int ni = 0, nf = 0;
    for (int i = threadIdx.x; i < 1024; i += 256) {
        unsigned int v = mw[i];
        if (v != 0u && v != 1u) ni = 1;
        if (v != 0u && v != 0x3F800000u) nf = 1;
    }
    if (ni) atomicOr(&notI32, 1);
    if (nf) atomicOr(&notF32, 1);
    __syncthreads();
    if (threadIdx.x == 0) g_mask_mode = (notI32 && notF32) ? 0 : 1;
}

// ---------------- fp32 -> s8 quantize (contiguous, x4) ----------------
__global__ __launch_bounds__(256)
void quant_kernel(const float* __restrict__ x, int8_t* __restrict__ y, int n4, float scale)
{
    int i = blockIdx.x * 256 + threadIdx.x;
    if (i >= n4) return;
    float4 v = ((const float4*)x)[i];
    int a = __float2int_rn(fminf(fmaxf(v.x * scale, -127.f), 127.f));
    int b = __float2int_rn(fminf(fmaxf(v.y * scale, -127.f), 127.f));
    int c = __float2int_rn(fminf(fmaxf(v.z * scale, -127.f), 127.f));
    int d = __float2int_rn(fminf(fmaxf(v.w * scale, -127.f), 127.f));
    uint32_t packed = (uint32_t)(a & 0xFF) | ((uint32_t)(b & 0xFF) << 8) |
                      ((uint32_t)(c & 0xFF) << 16) | ((uint32_t)(d & 0xFF) << 24);
    ((uint32_t*)y)[i] = packed;
}

// ---------------- W [512, Nn] -> Wt[Nn][512] quantized s8 ----------------
__global__ __launch_bounds__(256)
void wquant_kernel(const float* __restrict__ W, int8_t* __restrict__ Wt, int Nn)
{
    int idx = blockIdx.x * 256 + threadIdx.x;
    if (idx >= Nn * 512) return;
    int n = idx >> 9;
    int k = idx & 511;
    float v = W[(size_t)k * Nn + n] * W_SCALE;
    Wt[idx] = (int8_t)__float2int_rn(fminf(fmaxf(v, -127.f), 127.f));
}

// ---------------- W [512, 512] -> Wt fp16 ----------------
__global__ __launch_bounds__(256)
void wtrans_kernel(const float* __restrict__ W, __half* __restrict__ Wt, int Nn)
{
    int idx = blockIdx.x * 256 + threadIdx.x;
    if (idx >= Nn * 512) return;
    int n = idx >> 9;
    int k = idx & 511;
    Wt[idx] = __float2half_rn(W[(size_t)k * Nn + n]);
}

// ---------------- fp32 -> fp16 ----------------
__global__ __launch_bounds__(256)
void conv_f16_kernel(const float* __restrict__ x, __half* __restrict__ y, int n4)
{
    int i = blockIdx.x * 256 + threadIdx.x;
    if (i >= n4) return;
    float4 v = ((const float4*)x)[i];
    ((__half2*)y)[i * 2] = __floats2half2_rn(v.x, v.y);
    ((__half2*)y)[i * 2 + 1] = __floats2half2_rn(v.z, v.w);
}

// ---------------- INT8 IMMA GEMM: kvl = A[64000,512]s8 @ Bt[1536,512]s8^T -> fp16 ----------------
// 128x128 tile, BK=128 int8 bytes, 4 chunks, 3-stage cp.async, one sync per chunk.
// smem = 3 * 32768 = 98304. 2 CTAs/SM. grid (12, 500), 256 threads.
__global__ __launch_bounds__(256, 2)
void imma_gemm(const int8_t* __restrict__ A, const int8_t* __restrict__ Bt,
               __half* __restrict__ C, int Nn)
{
    extern __shared__ char dsm[];
    const uint32_t sb = smem_u32(dsm);
    const int tid = threadIdx.x;
    const int bm = blockIdx.y * 128;
    const int bn = blockIdx.x * 128;
    const int lane = tid & 31, w = tid >> 5;
    const int wr = w >> 2;   // 0..1: 64 m-rows
    const int wc = w & 3;    // 0..3: 32 n-cols

    const char* Ag = (const char*)A + (size_t)bm * 512;   // 512 B per row
    const char* Bg = (const char*)Bt + (size_t)bn * 512;

#define LOAD_CHUNK(kc)                                                      \
    do {                                                                    \
        uint32_t st_ = sb + ((kc) % 3) * 32768;                             \
        size_t gk_ = (size_t)(kc) * 128;                                    \
        _Pragma("unroll")                                                   \
        for (int i_ = 0; i_ < 4; i_++) {                                    \
            int g_ = tid + i_ * 256;                                        \
            int row_ = g_ >> 3, ch_ = g_ & 7;                               \
            uint32_t off_ = row_ * 128 + ch_ * 16;                          \
            uint32_t sw_ = off_ ^ ((off_ >> 3) & 0x70);                     \
            size_t go_ = (size_t)row_ * 512 + gk_ + ch_ * 16;               \
            cp_async16(st_ + sw_, Ag + go_);                                \
            cp_async16(st_ + 16384 + sw_, Bg + go_);                        \
        }                                                                   \
        cp_commit();                                                        \
    } while (0)

    int acc[4][4][4];
#pragma unroll
    for (int i = 0; i < 4; i++)
#pragma unroll
        for (int j = 0; j < 4; j++)
#pragma unroll
            for (int r = 0; r < 4; r++) acc[i][j][r] = 0;

    LOAD_CHUNK(0);
    LOAD_CHUNK(1);

    const int a_row = (lane & 15);
    const int a_c16 = (lane >> 4);
    const int b_nrow = (lane & 7) + ((lane >> 4) & 1) * 8;
    const int b_c16 = (lane >> 3) & 1;

    for (int kc = 0; kc < 4; ++kc) {
        if (kc == 3) cp_wait0(); else cp_wait1();
        __syncthreads();
        if (kc + 2 < 4) LOAD_CHUNK(kc + 2);

        uint32_t st = sb + (kc % 3) * 32768;
#pragma unroll
        for (int ks = 0; ks < 4; ++ks) {          // 32 int8 k-bytes per step
            uint32_t af[4][4];
#pragma unroll
            for (int mi = 0; mi < 4; ++mi) {
                uint32_t off = (uint32_t)(wr * 64 + mi * 16 + a_row) * 128 + ks * 32 + a_c16 * 16;
                uint32_t sw = off ^ ((off >> 3) & 0x70);
                ldsm_x4(af[mi][0], af[mi][1], af[mi][2], af[mi][3], st + sw);
            }
            uint32_t bf[2][4];
#pragma unroll
            for (int pr = 0; pr < 2; ++pr) {
                uint32_t off = (uint32_t)(wc * 32 + pr * 16 + b_nrow) * 128 + ks * 32 + b_c16 * 16;
                uint32_t sw = off ^ ((off >> 3) & 0x70);
                ldsm_x4(bf[pr][0], bf[pr][1], bf[pr][2], bf[pr][3], st + 16384 + sw);
            }
#pragma unroll
            for (int mi = 0; mi < 4; ++mi) {
#pragma unroll
                for (int pr = 0; pr < 2; ++pr) {
                    imma16832(acc[mi][pr * 2][0], acc[mi][pr * 2][1],
                              acc[mi][pr * 2][2], acc[mi][pr * 2][3],
                              af[mi][0], af[mi][1], af[mi][2], af[mi][3],
                              bf[pr][0], bf[pr][1]);
                    imma16832(acc[mi][pr * 2 + 1][0], acc[mi][pr * 2 + 1][1],
                              acc[mi][pr * 2 + 1][2], acc[mi][pr * 2 + 1][3],
                              af[mi][0], af[mi][1], af[mi][2], af[mi][3],
                              bf[pr][2], bf[pr][3]);
                }
            }
        }
    }
    __syncthreads();

#pragma unroll
    for (int mi = 0; mi < 4; ++mi) {
        int row0 = bm + wr * 64 + mi * 16 + (lane >> 2);
#pragma unroll
        for (int ni = 0; ni < 4; ++ni) {
            int col = bn + wc * 32 + ni * 8 + (lane & 3) * 2;
            *(__half2*)(C + (size_t)row0 * Nn + col) =
                __floats2half2_rn((float)acc[mi][ni][0] * DEQ_SCALE,
                                  (float)acc[mi][ni][1] * DEQ_SCALE);
            *(__half2*)(C + (size_t)(row0 + 8) * Nn + col) =
                __floats2half2_rn((float)acc[mi][ni][2] * DEQ_SCALE,
                                  (float)acc[mi][ni][3] * DEQ_SCALE);
        }
    }
#undef LOAD_CHUNK
}

// ---------------- fp16 HMMA GEMM (glimpse): C fp32 ----------------
__global__ __launch_bounds__(256, 2)
void hmma_gemm(const __half* __restrict__ A, const __half* __restrict__ Bt,
               float* __restrict__ C, int Nn)
{
    extern __shared__ char dsm[];
    const uint32_t sb = smem_u32(dsm);
    const int tid = threadIdx.x;
    const int bm = blockIdx.y * 128;
    const int bn = blockIdx.x * 128;
    const int lane = tid & 31, w = tid >> 5;
    const int wr = w >> 2;
    const int wc = w & 3;

    const char* Ag = (const char*)A + (size_t)bm * 1024;
    const char* Bg = (const char*)Bt + (size_t)bn * 1024;

#define LOAD_CHUNK(kc)                                                      \
    do {                                                                    \
        uint32_t st_ = sb + ((kc) & 1) * 32768;                             \
        size_t gk_ = (size_t)(kc) * 128;                                    \
        _Pragma("unroll")                                                   \
        for (int i_ = 0; i_ < 4; i_++) {                                    \
            int g_ = tid + i_ * 256;                                        \
            int row_ = g_ >> 3, ch_ = g_ & 7;                               \
            uint32_t off_ = row_ * 128 + ch_ * 16;                          \
            uint32_t sw_ = off_ ^ ((off_ >> 3) & 0x70);                     \
            size_t go_ = (size_t)row_ * 1024 + gk_ + ch_ * 16;              \
            cp_async16(st_ + sw_, Ag + go_);                                \
            cp_async16(st_ + 16384 + sw_, Bg + go_);                        \
        }                                                                   \
        cp_commit();                                                        \
    } while (0)

    float acc[4][4][4];
#pragma unroll
    for (int i = 0; i < 4; i++)
#pragma unroll
        for (int j = 0; j < 4; j++)
#pragma unroll
            for (int r = 0; r < 4; r++) acc[i][j][r] = 0.f;

    LOAD_CHUNK(0);

    const int a_row = (lane & 15);
    const int a_c16 = (lane >> 4);
    const int b_nrow = (lane & 7) + ((lane >> 4) & 1) * 8;
    const int b_c16 = (lane >> 3) & 1;

    for (int kc = 0; kc < 8; ++kc) {
        if (kc + 1 < 8) { LOAD_CHUNK(kc + 1); cp_wait1(); } else { cp_wait0(); }
        __syncthreads();

        uint32_t st = sb + (kc & 1) * 32768;
#pragma unroll
        for (int ks = 0; ks < 4; ++ks) {
            uint32_t af[4][4];
#pragma unroll
            for (int mi = 0; mi < 4; ++mi) {
                uint32_t off = (uint32_t)(wr * 64 + mi * 16 + a_row) * 128 + ks * 32 + a_c16 * 16;
                uint32_t sw = off ^ ((off >> 3) & 0x70);
                ldsm_x4(af[mi][0], af[mi][1], af[mi][2], af[mi][3], st + sw);
            }
            uint32_t bf[2][4];
#pragma unroll
            for (int pr = 0; pr < 2; ++pr) {
                uint32_t off = (uint32_t)(wc * 32 + pr * 16 + b_nrow) * 128 + ks * 32 + b_c16 * 16;
                uint32_t sw = off ^ ((off >> 3) & 0x70);
                ldsm_x4(bf[pr][0], bf[pr][1], bf[pr][2], bf[pr][3], st + 16384 + sw);
            }
#pragma unroll
            for (int mi = 0; mi < 4; ++mi) {
#pragma unroll
                for (int pr = 0; pr < 2; ++pr) {
                    mma16816(acc[mi][pr * 2][0], acc[mi][pr * 2][1],
                             acc[mi][pr * 2][2], acc[mi][pr * 2][3],
                             af[mi][0], af[mi][1], af[mi][2], af[mi][3],
                             bf[pr][0], bf[pr][1]);
                    mma16816(acc[mi][pr * 2 + 1][0], acc[mi][pr * 2 + 1][1],
                             acc[mi][pr * 2 + 1][2], acc[mi][pr * 2 + 1][3],
                             af[mi][0], af[mi][1], af[mi][2], af[mi][3],
                             bf[pr][2], bf[pr][3]);
                }
            }
        }
        __syncthreads();
    }

#pragma unroll
    for (int mi = 0; mi < 4; ++mi) {
        int row0 = bm + wr * 64 + mi * 16 + (lane >> 2);
#pragma unroll
        for (int ni = 0; ni < 4; ++ni) {
            int col = bn + wc * 32 + ni * 8 + (lane & 3) * 2;
            *(float2*)(C + (size_t)row0 * Nn + col) = make_float2(acc[mi][ni][0], acc[mi][ni][1]);
            *(float2*)(C + (size_t)(row0 + 8) * Nn + col) = make_float2(acc[mi][ni][2], acc[mi][ni][3]);
        }
    }
#undef LOAD_CHUNK
}

// ---------------- flash-style masked MHA (reads fp16 kvl) ----------------
__global__ __launch_bounds__(640)
void attn_kernel(const float* __restrict__ qin, const void* __restrict__ mask)
{
    __shared__ __align__(16) float sq[20][64];
    __shared__ __align__(16) float sk[40][64];
    __shared__ __align__(16) float sv[40][64];
    const int h = blockIdx.x, b = blockIdx.y;
    const int tid = threadIdx.x;
    const int mode = g_mask_mode;

    if (tid < 320) {
        int s = tid >> 4, dg = (tid & 15) << 2;
        *(float4*)&sq[s][dg] = *(const float4*)(qin + (size_t)(b * 20 + s) * 512 + h * 64 + dg);
    }

    const int lane = tid & 31, w = tid >> 5;
    float m = -1e30f, l = 0.f, acc0 = 0.f, acc1 = 0.f;
    float q0 = 0.f, q1 = 0.f;

    const int nn = tid >> 4;
    const int dg = (tid & 15) << 2;

    for (int t = 0; t < 25; ++t) {
        const int n0 = t * 40;
        __syncthreads();
        {
            const __half* base = g_kvlh + (size_t)(b * 1000 + n0 + nn) * 1536 + h * 64 + dg;
            __half2 k01 = *(const __half2*)(base);
            __half2 k23 = *(const __half2*)(base + 2);
            __half2 v01 = *(const __half2*)(base + 512);
            __half2 v23 = *(const __half2*)(base + 514);
            float2 kf0 = __half22float2(k01), kf1 = __half22float2(k23);
            float2 vf0 = __half22float2(v01), vf1 = __half22float2(v23);
            *(float4*)&sk[nn][dg] = make_float4(kf0.x, kf0.y, kf1.x, kf1.y);
            *(float4*)&sv[nn][dg] = make_float4(vf0.x, vf0.y, vf1.x, vf1.y);
        }
        __syncthreads();
        if (w < 20) {
            if (t == 0) { q0 = sq[w][lane]; q1 = sq[w][lane + 32]; }
            const int midx0 = (b * 20 + w) * 1000 + n0;
#pragma unroll 4
            for (int n = 0; n < 40; ++n) {
                float x = q0 * sk[n][lane] + q1 * sk[n][lane + 32];
                x += __shfl_xor_sync(0xffffffffu, x, 16);
                x += __shfl_xor_sync(0xffffffffu, x, 8);
                x += __shfl_xor_sync(0xffffffffu, x, 4);
                x += __shfl_xor_sync(0xffffffffu, x, 2);
                x += __shfl_xor_sync(0xffffffffu, x, 1);
                x *= INV_SQRT_DK;
                if (is_feasible(mask, midx0 + n, mode)) {
                    float mn = fmaxf(m, x);
                    float corr = __expf(m - mn);
                    float p = __expf(x - mn);
                    l = l * corr + p;
                    acc0 = acc0 * corr + p * sv[n][lane];
                    acc1 = acc1 * corr + p * sv[n][lane + 32];
                    m = mn;
                }
            }
        }
    }
    if (w < 20) {
        float inv = 1.f / l;
        size_t o = (size_t)(b * 20 + w) * 512 + h * 64 + lane;
        g_heads[o] = acc0 * inv;
        g_heads[o + 32] = acc1 * inv;
    }
}

// ---------------- pointer logits (reads fp16 logit_k) ----------------
__global__ __launch_bounds__(256)
void pointer_kernel(const void* __restrict__ mask)
{
    __shared__ __align__(16) float sg[10 * 512];
    __shared__ __align__(16) float slk[8 * 512];
    const int b = blockIdx.x;
    const int sbase = blockIdx.y * 10;
    const int nsl = blockIdx.z;
    const int tid = threadIdx.x;
    const int mode = g_mask_mode;

    for (int i = tid; i < 10 * 512 / 4; i += 256) {
        int off = i << 2;
        int s = off >> 9, d = off & 511;
        *(float4*)&sg[off] = *(const float4*)(g_glimpse + (size_t)(b * 20 + sbase + s) * 512 + d);
    }

    const int lane = tid & 31, w = tid >> 5;
    for (int t = 0; t < 25; ++t) {
        const int n0 = nsl * 200 + t * 8;
        __syncthreads();
        for (int i = tid; i < 8 * 512 / 8; i += 256) {
            int off = i << 3;
            int nn = off >> 9, d = off & 511;
            const __half* src = g_kvlh + (size_t)(b * 1000 + n0 + nn) * 1536 + 1024 + d;
            uint4 raw = *(const uint4*)src;
            const __half2* hp = (const __half2*)&raw;
            float2 f0 = __half22float2(hp[0]);
            float2 f1 = __half22float2(hp[1]);
            float2 f2 = __half22float2(hp[2]);
            float2 f3 = __half22float2(hp[3]);
            *(float4*)&slk[off] = make_float4(f0.x, f0.y, f1.x, f1.y);
            *(float4*)&slk[off + 4] = make_float4(f2.x, f2.y, f3.x, f3.y);
        }
        __syncthreads();
#pragma unroll
        for (int pp = 0; pp < 10; ++pp) {
            const int p = w * 10 + pp;
            const int sl = p >> 3, n = p & 7;
            const float* gr = &sg[sl * 512];
            const float* kr = &slk[n * 512];
            float sum = 0.f;
#pragma unroll
            for (int i = 0; i < 16; ++i)
                sum += gr[lane + i * 32] * kr[lane + i * 32];
            sum = warp_sum(sum);
            if (lane == 0) {
                float lg = 10.f * tanhf(sum * INV_SQRT_D);
                int gidx = (b * 20 + sbase + sl) * 1000 + n0 + n;
                if (!is_feasible(mask, gidx, mode)) lg = NEG_BIG;
                g_logits[gidx] = lg;
            }
        }
    }
}

// ---------------- log-softmax + transposed writeout ----------------
__global__ __launch_bounds__(256)
void lsm_kernel(float* __restrict__ out)
{
    const int s = blockIdx.x, b = blockIdx.y;
    const float* row = g_logits + (size_t)(b * 20 + s) * 1000;
    float* orow = out + (size_t)(s * 64 + b) * 1000;
    __shared__ float red[8];
    const int tid = threadIdx.x;
    const int lane = tid & 31, w = tid >> 5;

    float mx = -1e30f;
    for (int i = tid; i < 1000; i += 256) mx = fmaxf(mx, row[i]);
    mx = warp_max(mx);
    if (lane == 0) red[w] = mx;
    __syncthreads();
    if (w == 0) {
        float v = (lane < 8) ? red[lane] : -1e30f;
        v = warp_max(v);
        if (lane == 0) red[0] = v;
    }
    __syncthreads();
    mx = red[0];
    __syncthreads();

    float se = 0.f;
    for (int i = tid; i < 1000; i += 256) se += __expf(row[i] - mx);
    se = warp_sum(se);
    if (lane == 0) red[w] = se;
    __syncthreads();
    if (w == 0) {
        float v = (lane < 8) ? red[lane] : 0.f;
        v = warp_sum(v);
        if (lane == 0) red[0] = v;
    }
    __syncthreads();
    const float lse = mx + logf(red[0]);

    for (int i = tid; i < 1000; i += 256) orow[i] = row[i] - lse;
}

// ---------------- launch ----------------
extern "C" void kernel_launch(void* const* d_in, const int* in_sizes, int n_in,
                              void* d_out, int out_size)
{
    (void)out_size;
    const float* emb = nullptr;
    const float* q = nullptr;
    const void* mask = nullptr;
    const float* Wkvl = nullptr;
    const float* Wout = nullptr;
    for (int i = 0; i < n_in; ++i) {
        switch (in_sizes[i]) {
            case 32768000: emb = (const float*)d_in[i]; break;
            case 655360:   q = (const float*)d_in[i]; break;
            case 1280000:  mask = d_in[i]; break;
            case 786432:   Wkvl = (const float*)d_in[i]; break;
            case 262144:   Wout = (const float*)d_in[i]; break;
            default: break;
        }
    }
    float* out = (float*)d_out;

    float *headsp, *glimpsep;
    __half *kvlhp, *wot, *hf16;
    int8_t *as8, *wks8;
    cudaGetSymbolAddress((void**)&kvlhp, g_kvlh);
    cudaGetSymbolAddress((void**)&headsp, g_heads);
    cudaGetSymbolAddress((void**)&glimpsep, g_glimpse);
    cudaGetSymbolAddress((void**)&as8, g_As8);
    cudaGetSymbolAddress((void**)&wks8, g_Wkvl_s8);
    cudaGetSymbolAddress((void**)&wot, g_Wout_t);
    cudaGetSymbolAddress((void**)&hf16, g_Hf16);

    cudaFuncSetAttribute(imma_gemm, cudaFuncAttributeMaxDynamicSharedMemorySize, 98304);
    cudaFuncSetAttribute(hmma_gemm, cudaFuncAttributeMaxDynamicSharedMemorySize, 65536);

    detect_mask_kernel<<<1, 256>>>((const unsigned int*)mask);

    // quantize / transpose
    quant_kernel<<<32000, 256>>>(emb, as8, 8192000, EMB_SCALE);
    wquant_kernel<<<3072, 256>>>(Wkvl, wks8, 1536);
    wtrans_kernel<<<1024, 256>>>(Wout, wot, 512);

    // kvl = embeddings @ W_kvl  [64000 x 1536] int8 -> fp16
    {
        dim3 grid(12, 500);
        imma_gemm<<<grid, 256, 98304>>>(as8, wks8, kvlhp, 1536);
    }

    // attention
    {
        dim3 grid(8, 64);
        attn_kernel<<<grid, 640>>>(q, mask);
    }

    // glimpse = heads @ W_out  [1280 x 512] fp16 -> fp32
    conv_f16_kernel<<<640, 256>>>(headsp, hf16, 163840);
    {
        dim3 grid(4, 10);
        hmma_gemm<<<grid, 256, 65536>>>(hf16, wot, glimpsep, 512);
    }

    // pointer logits
    {
        dim3 grid(64, 2, 5);
        pointer_kernel<<<grid, 256>>>(mask);
    }

    // log-softmax
    {
        dim3 grid(20, 64);
        lsm_kernel<<<grid, 256>>>(out);
    }
}

// round 6
// speedup vs baseline: 1.3484x; 1.3484x over previous
#include <cuda_runtime.h>
#include <cuda_fp16.h>
#include <cstdint>

// B=64, N=1000, D=512, H=8, S=20, DK=64
#define NEG_BIG (-1e9f)
#define INV_SQRT_DK 0.125f
#define INV_SQRT_D 0.04419417382415922f

// ---------------- device scratch ----------------
__device__ __align__(16) __half g_kvlh[64000 * 1536];    // fp16 [b*1000+n][gk|gv|lk]
__device__ __align__(16) float g_heads[1280 * 512];
__device__ __align__(16) float g_glimpse[1280 * 512];
__device__ __align__(16) float g_logits[1280 * 1000];
__device__ __align__(16) __half g_Af16[64000 * 512];
__device__ __align__(16) __half g_Wkvl_t[1536 * 512];
__device__ __align__(16) __half g_Wout_t[512 * 512];
__device__ __align__(16) __half g_Hf16[1280 * 512];
__device__ int g_mask_mode;

// ---------------- helpers ----------------
__device__ __forceinline__ bool is_feasible(const void* mp, int idx, int mode) {
    if (mode) return ((const unsigned int*)mp)[idx] != 0u;
    return ((const unsigned char*)mp)[idx] != 0;
}
__device__ __forceinline__ float warp_max(float v) {
#pragma unroll
    for (int o = 16; o; o >>= 1) v = fmaxf(v, __shfl_xor_sync(0xffffffffu, v, o));
    return v;
}
__device__ __forceinline__ float warp_sum(float v) {
#pragma unroll
    for (int o = 16; o; o >>= 1) v += __shfl_xor_sync(0xffffffffu, v, o);
    return v;
}
__device__ __forceinline__ uint32_t smem_u32(const void* p) {
    uint32_t a;
    asm("{ .reg .u64 t; cvta.to.shared.u64 t, %1; cvt.u32.u64 %0, t; }" : "=r"(a) : "l"(p));
    return a;
}
__device__ __forceinline__ void cp_async16(uint32_t saddr, const void* gaddr) {
    asm volatile("cp.async.cg.shared.global [%0], [%1], 16;" :: "r"(saddr), "l"(gaddr));
}
__device__ __forceinline__ void cp_commit() { asm volatile("cp.async.commit_group;" ::: "memory"); }
__device__ __forceinline__ void cp_wait1() { asm volatile("cp.async.wait_group 1;" ::: "memory"); }
__device__ __forceinline__ void cp_wait0() { asm volatile("cp.async.wait_group 0;" ::: "memory"); }

__device__ __forceinline__ void ldsm_x4(uint32_t& r0, uint32_t& r1, uint32_t& r2, uint32_t& r3,
                                        uint32_t addr) {
    asm volatile("ldmatrix.sync.aligned.m8n8.x4.shared.b16 {%0,%1,%2,%3}, [%4];"
                 : "=r"(r0), "=r"(r1), "=r"(r2), "=r"(r3) : "r"(addr));
}
__device__ __forceinline__ void mma16816(float& c0, float& c1, float& c2, float& c3,
                                         uint32_t a0, uint32_t a1, uint32_t a2, uint32_t a3,
                                         uint32_t b0, uint32_t b1) {
    asm volatile(
        "mma.sync.aligned.m16n8k16.row.col.f32.f16.f16.f32 "
        "{%0,%1,%2,%3}, {%4,%5,%6,%7}, {%8,%9}, {%0,%1,%2,%3};"
        : "+f"(c0), "+f"(c1), "+f"(c2), "+f"(c3)
        : "r"(a0), "r"(a1), "r"(a2), "r"(a3), "r"(b0), "r"(b1));
}

// ---------------- mask dtype sniffer ----------------
__global__ void detect_mask_kernel(const unsigned int* mw) {
    __shared__ int notI32, notF32;
    if (threadIdx.x == 0) { notI32 = 0; notF32 = 0; }
    __syncthreads();
    int ni = 0, nf = 0;
    for (int i = threadIdx.x; i < 1024; i += 256) {
        unsigned int v = mw[i];
        if (v != 0u && v != 1u) ni = 1;
        if (v != 0u && v != 0x3F800000u) nf = 1;
    }
    if (ni) atomicOr(&notI32, 1);
    if (nf) atomicOr(&notF32, 1);
    __syncthreads();
    if (threadIdx.x == 0) g_mask_mode = (notI32 && notF32) ? 0 : 1;
}

// ---------------- fp32 -> fp16 ----------------
__global__ __launch_bounds__(256)
void conv_f16_kernel(const float* __restrict__ x, __half* __restrict__ y, int n4)
{
    int i = blockIdx.x * 256 + threadIdx.x;
    if (i >= n4) return;
    float4 v = ((const float4*)x)[i];
    ((__half2*)y)[i * 2] = __floats2half2_rn(v.x, v.y);
    ((__half2*)y)[i * 2 + 1] = __floats2half2_rn(v.z, v.w);
}

// ---------------- W [512, Nn] -> Wt[Nn][512] fp16 ----------------
__global__ __launch_bounds__(256)
void wtrans_kernel(const float* __restrict__ W, __half* __restrict__ Wt, int Nn)
{
    int idx = blockIdx.x * 256 + threadIdx.x;
    if (idx >= Nn * 512) return;
    int n = idx >> 9;
    int k = idx & 511;
    Wt[idx] = __float2half_rn(W[(size_t)k * Nn + n]);
}

// ---------------- BIG fp16 HMMA GEMM: 128x256 tile, 8 warps (64x64 each) ----------------
// C[M,Nn] = A[M,512] @ Bt[Nn,512]^T -> fp16. BK=64, 3-stage cp.async, one sync/chunk.
// smem/stage: A 16K + B 32K = 48K; 3 stages = 147456 B. 1 CTA/SM.
// grid (Nn/256, M/128), 256 threads.
__global__ __launch_bounds__(256)
void hmma_gemm_big(const __half* __restrict__ A, const __half* __restrict__ Bt,
                   __half* __restrict__ C, int Nn)
{
    extern __shared__ char dsm[];
    const uint32_t sb = smem_u32(dsm);
    const int tid = threadIdx.x;
    const int bm = blockIdx.y * 128;
    const int bn = blockIdx.x * 256;
    const int lane = tid & 31, w = tid >> 5;
    const int wr = w >> 2;   // 0..1 : 64 m-rows
    const int wc = w & 3;    // 0..3 : 64 n-cols

    const char* Ag = (const char*)A + (size_t)bm * 1024;
    const char* Bg = (const char*)Bt + (size_t)bn * 1024;

    // stage layout: A at +0 (16 KB), B at +16384 (32 KB); stride 49152
#define LOAD_CHUNK(kc)                                                      \
    do {                                                                    \
        uint32_t st_ = sb + ((kc) % 3) * 49152;                             \
        size_t gk_ = (size_t)(kc) * 128;                                    \
        _Pragma("unroll")                                                   \
        for (int i_ = 0; i_ < 4; i_++) {                                    \
            int g_ = tid + i_ * 256;                                        \
            int row_ = g_ >> 3, ch_ = g_ & 7;                               \
            uint32_t off_ = row_ * 128 + ch_ * 16;                          \
            uint32_t sw_ = off_ ^ ((off_ >> 3) & 0x70);                     \
            cp_async16(st_ + sw_, Ag + (size_t)row_ * 1024 + gk_ + ch_ * 16); \
        }                                                                   \
        _Pragma("unroll")                                                   \
        for (int i_ = 0; i_ < 8; i_++) {                                    \
            int g_ = tid + i_ * 256;                                        \
            int row_ = g_ >> 3, ch_ = g_ & 7;                               \
            uint32_t off_ = row_ * 128 + ch_ * 16;                          \
            uint32_t sw_ = off_ ^ ((off_ >> 3) & 0x70);                     \
            cp_async16(st_ + 16384 + sw_, Bg + (size_t)row_ * 1024 + gk_ + ch_ * 16); \
        }                                                                   \
        cp_commit();                                                        \
    } while (0)

    float acc[4][8][4];
#pragma unroll
    for (int i = 0; i < 4; i++)
#pragma unroll
        for (int j = 0; j < 8; j++)
#pragma unroll
            for (int r = 0; r < 4; r++) acc[i][j][r] = 0.f;

    LOAD_CHUNK(0);
    LOAD_CHUNK(1);

    const int a_row = (lane & 15);
    const int a_c16 = (lane >> 4);
    const int b_nrow = (lane & 7) + ((lane >> 4) & 1) * 8;
    const int b_c16 = (lane >> 3) & 1;

    for (int kc = 0; kc < 8; ++kc) {
        if (kc == 7) cp_wait0(); else cp_wait1();
        __syncthreads();
        if (kc + 2 < 8) LOAD_CHUNK(kc + 2);

        uint32_t st = sb + (kc % 3) * 49152;
#pragma unroll
        for (int ks = 0; ks < 4; ++ks) {
            uint32_t af[4][4];
#pragma unroll
            for (int mi = 0; mi < 4; ++mi) {
                uint32_t off = (uint32_t)(wr * 64 + mi * 16 + a_row) * 128 + ks * 32 + a_c16 * 16;
                uint32_t sw = off ^ ((off >> 3) & 0x70);
                ldsm_x4(af[mi][0], af[mi][1], af[mi][2], af[mi][3], st + sw);
            }
            uint32_t bf[4][4];
#pragma unroll
            for (int pr = 0; pr < 4; ++pr) {
                uint32_t off = (uint32_t)(wc * 64 + pr * 16 + b_nrow) * 128 + ks * 32 + b_c16 * 16;
                uint32_t sw = off ^ ((off >> 3) & 0x70);
                ldsm_x4(bf[pr][0], bf[pr][1], bf[pr][2], bf[pr][3], st + 16384 + sw);
            }
#pragma unroll
            for (int mi = 0; mi < 4; ++mi) {
#pragma unroll
                for (int pr = 0; pr < 4; ++pr) {
                    mma16816(acc[mi][pr * 2][0], acc[mi][pr * 2][1],
                             acc[mi][pr * 2][2], acc[mi][pr * 2][3],
                             af[mi][0], af[mi][1], af[mi][2], af[mi][3],
                             bf[pr][0], bf[pr][1]);
                    mma16816(acc[mi][pr * 2 + 1][0], acc[mi][pr * 2 + 1][1],
                             acc[mi][pr * 2 + 1][2], acc[mi][pr * 2 + 1][3],
                             af[mi][0], af[mi][1], af[mi][2], af[mi][3],
                             bf[pr][2], bf[pr][3]);
                }
            }
        }
    }
    __syncthreads();

#pragma unroll
    for (int mi = 0; mi < 4; ++mi) {
        int row0 = bm + wr * 64 + mi * 16 + (lane >> 2);
#pragma unroll
        for (int ni = 0; ni < 8; ++ni) {
            int col = bn + wc * 64 + ni * 8 + (lane & 3) * 2;
            *(__half2*)(C + (size_t)row0 * Nn + col) =
                __floats2half2_rn(acc[mi][ni][0], acc[mi][ni][1]);
            *(__half2*)(C + (size_t)(row0 + 8) * Nn + col) =
                __floats2half2_rn(acc[mi][ni][2], acc[mi][ni][3]);
        }
    }
#undef LOAD_CHUNK
}

// ---------------- small fp16 HMMA GEMM (glimpse): 128x128, fp32 out ----------------
__global__ __launch_bounds__(256, 2)
void hmma_gemm(const __half* __restrict__ A, const __half* __restrict__ Bt,
               float* __restrict__ C, int Nn)
{
    extern __shared__ char dsm[];
    const uint32_t sb = smem_u32(dsm);
    const int tid = threadIdx.x;
    const int bm = blockIdx.y * 128;
    const int bn = blockIdx.x * 128;
    const int lane = tid & 31, w = tid >> 5;
    const int wr = w >> 2;
    const int wc = w & 3;

    const char* Ag = (const char*)A + (size_t)bm * 1024;
    const char* Bg = (const char*)Bt + (size_t)bn * 1024;

#define LOAD_CHUNK(kc)                                                      \
    do {                                                                    \
        uint32_t st_ = sb + ((kc) & 1) * 32768;                             \
        size_t gk_ = (size_t)(kc) * 128;                                    \
        _Pragma("unroll")                                                   \
        for (int i_ = 0; i_ < 4; i_++) {                                    \
            int g_ = tid + i_ * 256;                                        \
            int row_ = g_ >> 3, ch_ = g_ & 7;                               \
            uint32_t off_ = row_ * 128 + ch_ * 16;                          \
            uint32_t sw_ = off_ ^ ((off_ >> 3) & 0x70);                     \
            size_t go_ = (size_t)row_ * 1024 + gk_ + ch_ * 16;              \
            cp_async16(st_ + sw_, Ag + go_);                                \
            cp_async16(st_ + 16384 + sw_, Bg + go_);                        \
        }                                                                   \
        cp_commit();                                                        \
    } while (0)

    float acc[4][4][4];
#pragma unroll
    for (int i = 0; i < 4; i++)
#pragma unroll
        for (int j = 0; j < 4; j++)
#pragma unroll
            for (int r = 0; r < 4; r++) acc[i][j][r] = 0.f;

    LOAD_CHUNK(0);

    const int a_row = (lane & 15);
    const int a_c16 = (lane >> 4);
    const int b_nrow = (lane & 7) + ((lane >> 4) & 1) * 8;
    const int b_c16 = (lane >> 3) & 1;

    for (int kc = 0; kc < 8; ++kc) {
        if (kc + 1 < 8) { LOAD_CHUNK(kc + 1); cp_wait1(); } else { cp_wait0(); }
        __syncthreads();

        uint32_t st = sb + (kc & 1) * 32768;
#pragma unroll
        for (int ks = 0; ks < 4; ++ks) {
            uint32_t af[4][4];
#pragma unroll
            for (int mi = 0; mi < 4; ++mi) {
                uint32_t off = (uint32_t)(wr * 64 + mi * 16 + a_row) * 128 + ks * 32 + a_c16 * 16;
                uint32_t sw = off ^ ((off >> 3) & 0x70);
                ldsm_x4(af[mi][0], af[mi][1], af[mi][2], af[mi][3], st + sw);
            }
            uint32_t bf[2][4];
#pragma unroll
            for (int pr = 0; pr < 2; ++pr) {
                uint32_t off = (uint32_t)(wc * 32 + pr * 16 + b_nrow) * 128 + ks * 32 + b_c16 * 16;
                uint32_t sw = off ^ ((off >> 3) & 0x70);
                ldsm_x4(bf[pr][0], bf[pr][1], bf[pr][2], bf[pr][3], st + 16384 + sw);
            }
#pragma unroll
            for (int mi = 0; mi < 4; ++mi) {
#pragma unroll
                for (int pr = 0; pr < 2; ++pr) {
                    mma16816(acc[mi][pr * 2][0], acc[mi][pr * 2][1],
                             acc[mi][pr * 2][2], acc[mi][pr * 2][3],
                             af[mi][0], af[mi][1], af[mi][2], af[mi][3],
                             bf[pr][0], bf[pr][1]);
                    mma16816(acc[mi][pr * 2 + 1][0], acc[mi][pr * 2 + 1][1],
                             acc[mi][pr * 2 + 1][2], acc[mi][pr * 2 + 1][3],
                             af[mi][0], af[mi][1], af[mi][2], af[mi][3],
                             bf[pr][2], bf[pr][3]);
                }
            }
        }
        __syncthreads();
    }

#pragma unroll
    for (int mi = 0; mi < 4; ++mi) {
        int row0 = bm + wr * 64 + mi * 16 + (lane >> 2);
#pragma unroll
        for (int ni = 0; ni < 4; ++ni) {
            int col = bn + wc * 32 + ni * 8 + (lane & 3) * 2;
            *(float2*)(C + (size_t)row0 * Nn + col) = make_float2(acc[mi][ni][0], acc[mi][ni][1]);
            *(float2*)(C + (size_t)(row0 + 8) * Nn + col) = make_float2(acc[mi][ni][2], acc[mi][ni][3]);
        }
    }
#undef LOAD_CHUNK
}

// ---------------- flash-style masked MHA (reads fp16 kvl) ----------------
__global__ __launch_bounds__(640)
void attn_kernel(const float* __restrict__ qin, const void* __restrict__ mask)
{
    __shared__ __align__(16) float sq[20][64];
    __shared__ __align__(16) float sk[40][64];
    __shared__ __align__(16) float sv[40][64];
    const int h = blockIdx.x, b = blockIdx.y;
    const int tid = threadIdx.x;
    const int mode = g_mask_mode;

    if (tid < 320) {
        int s = tid >> 4, dg = (tid & 15) << 2;
        *(float4*)&sq[s][dg] = *(const float4*)(qin + (size_t)(b * 20 + s) * 512 + h * 64 + dg);
    }

    const int lane = tid & 31, w = tid >> 5;
    float m = -1e30f, l = 0.f, acc0 = 0.f, acc1 = 0.f;
    float q0 = 0.f, q1 = 0.f;

    const int nn = tid >> 4;
    const int dg = (tid & 15) << 2;

    for (int t = 0; t < 25; ++t) {
        const int n0 = t * 40;
        __syncthreads();
        {
            const __half* base = g_kvlh + (size_t)(b * 1000 + n0 + nn) * 1536 + h * 64 + dg;
            __half2 k01 = *(const __half2*)(base);
            __half2 k23 = *(const __half2*)(base + 2);
            __half2 v01 = *(const __half2*)(base + 512);
            __half2 v23 = *(const __half2*)(base + 514);
            float2 kf0 = __half22float2(k01), kf1 = __half22float2(k23);
            float2 vf0 = __half22float2(v01), vf1 = __half22float2(v23);
            *(float4*)&sk[nn][dg] = make_float4(kf0.x, kf0.y, kf1.x, kf1.y);
            *(float4*)&sv[nn][dg] = make_float4(vf0.x, vf0.y, vf1.x, vf1.y);
        }
        __syncthreads();
        if (w < 20) {
            if (t == 0) { q0 = sq[w][lane]; q1 = sq[w][lane + 32]; }
            const int midx0 = (b * 20 + w) * 1000 + n0;
#pragma unroll 4
            for (int n = 0; n < 40; ++n) {
                float x = q0 * sk[n][lane] + q1 * sk[n][lane + 32];
                x += __shfl_xor_sync(0xffffffffu, x, 16);
                x += __shfl_xor_sync(0xffffffffu, x, 8);
                x += __shfl_xor_sync(0xffffffffu, x, 4);
                x += __shfl_xor_sync(0xffffffffu, x, 2);
                x += __shfl_xor_sync(0xffffffffu, x, 1);
                x *= INV_SQRT_DK;
                if (is_feasible(mask, midx0 + n, mode)) {
                    float mn = fmaxf(m, x);
                    float corr = __expf(m - mn);
                    float p = __expf(x - mn);
                    l = l * corr + p;
                    acc0 = acc0 * corr + p * sv[n][lane];
                    acc1 = acc1 * corr + p * sv[n][lane + 32];
                    m = mn;
                }
            }
        }
    }
    if (w < 20) {
        float inv = 1.f / l;
        size_t o = (size_t)(b * 20 + w) * 512 + h * 64 + lane;
        g_heads[o] = acc0 * inv;
        g_heads[o + 32] = acc1 * inv;
    }
}

// ---------------- pointer logits (reads fp16 logit_k) ----------------
__global__ __launch_bounds__(256)
void pointer_kernel(const void* __restrict__ mask)
{
    __shared__ __align__(16) float sg[10 * 512];
    __shared__ __align__(16) float slk[8 * 512];
    const int b = blockIdx.x;
    const int sbase = blockIdx.y * 10;
    const int nsl = blockIdx.z;
    const int tid = threadIdx.x;
    const int mode = g_mask_mode;

    for (int i = tid; i < 10 * 512 / 4; i += 256) {
        int off = i << 2;
        int s = off >> 9, d = off & 511;
        *(float4*)&sg[off] = *(const float4*)(g_glimpse + (size_t)(b * 20 + sbase + s) * 512 + d);
    }

    const int lane = tid & 31, w = tid >> 5;
    for (int t = 0; t < 25; ++t) {
        const int n0 = nsl * 200 + t * 8;
        __syncthreads();
        for (int i = tid; i < 8 * 512 / 8; i += 256) {
            int off = i << 3;
            int nn = off >> 9, d = off & 511;
            const __half* src = g_kvlh + (size_t)(b * 1000 + n0 + nn) * 1536 + 1024 + d;
            uint4 raw = *(const uint4*)src;
            const __half2* hp = (const __half2*)&raw;
            float2 f0 = __half22float2(hp[0]);
            float2 f1 = __half22float2(hp[1]);
            float2 f2 = __half22float2(hp[2]);
            float2 f3 = __half22float2(hp[3]);
            *(float4*)&slk[off] = make_float4(f0.x, f0.y, f1.x, f1.y);
            *(float4*)&slk[off + 4] = make_float4(f2.x, f2.y, f3.x, f3.y);
        }
        __syncthreads();
#pragma unroll
        for (int pp = 0; pp < 10; ++pp) {
            const int p = w * 10 + pp;
            const int sl = p >> 3, n = p & 7;
            const float* gr = &sg[sl * 512];
            const float* kr = &slk[n * 512];
            float sum = 0.f;
#pragma unroll
            for (int i = 0; i < 16; ++i)
                sum += gr[lane + i * 32] * kr[lane + i * 32];
            sum = warp_sum(sum);
            if (lane == 0) {
                float lg = 10.f * tanhf(sum * INV_SQRT_D);
                int gidx = (b * 20 + sbase + sl) * 1000 + n0 + n;
                if (!is_feasible(mask, gidx, mode)) lg = NEG_BIG;
                g_logits[gidx] = lg;
            }
        }
    }
}

// ---------------- log-softmax + transposed writeout ----------------
__global__ __launch_bounds__(256)
void lsm_kernel(float* __restrict__ out)
{
    const int s = blockIdx.x, b = blockIdx.y;
    const float* row = g_logits + (size_t)(b * 20 + s) * 1000;
    float* orow = out + (size_t)(s * 64 + b) * 1000;
    __shared__ float red[8];
    const int tid = threadIdx.x;
    const int lane = tid & 31, w = tid >> 5;

    float mx = -1e30f;
    for (int i = tid; i < 1000; i += 256) mx = fmaxf(mx, row[i]);
    mx = warp_max(mx);
    if (lane == 0) red[w] = mx;
    __syncthreads();
    if (w == 0) {
        float v = (lane < 8) ? red[lane] : -1e30f;
        v = warp_max(v);
        if (lane == 0) red[0] = v;
    }
    __syncthreads();
    mx = red[0];
    __syncthreads();

    float se = 0.f;
    for (int i = tid; i < 1000; i += 256) se += __expf(row[i] - mx);
    se = warp_sum(se);
    if (lane == 0) red[w] = se;
    __syncthreads();
    if (w == 0) {
        float v = (lane < 8) ? red[lane] : 0.f;
        v = warp_sum(v);
        if (lane == 0) red[0] = v;
    }
    __syncthreads();
    const float lse = mx + logf(red[0]);

    for (int i = tid; i < 1000; i += 256) orow[i] = row[i] - lse;
}

// ---------------- launch ----------------
extern "C" void kernel_launch(void* const* d_in, const int* in_sizes, int n_in,
                              void* d_out, int out_size)
{
    (void)out_size;
    const float* emb = nullptr;
    const float* q = nullptr;
    const void* mask = nullptr;
    const float* Wkvl = nullptr;
    const float* Wout = nullptr;
    for (int i = 0; i < n_in; ++i) {
        switch (in_sizes[i]) {
            case 32768000: emb = (const float*)d_in[i]; break;
            case 655360:   q = (const float*)d_in[i]; break;
            case 1280000:  mask = d_in[i]; break;
            case 786432:   Wkvl = (const float*)d_in[i]; break;
            case 262144:   Wout = (const float*)d_in[i]; break;
            default: break;
        }
    }
    float* out = (float*)d_out;

    float *headsp, *glimpsep;
    __half *kvlhp, *af16, *wkt, *wot, *hf16;
    cudaGetSymbolAddress((void**)&kvlhp, g_kvlh);
    cudaGetSymbolAddress((void**)&headsp, g_heads);
    cudaGetSymbolAddress((void**)&glimpsep, g_glimpse);
    cudaGetSymbolAddress((void**)&af16, g_Af16);
    cudaGetSymbolAddress((void**)&wkt, g_Wkvl_t);
    cudaGetSymbolAddress((void**)&wot, g_Wout_t);
    cudaGetSymbolAddress((void**)&hf16, g_Hf16);

    cudaFuncSetAttribute(hmma_gemm_big, cudaFuncAttributeMaxDynamicSharedMemorySize, 147456);
    cudaFuncSetAttribute(hmma_gemm, cudaFuncAttributeMaxDynamicSharedMemorySize, 65536);

    // Launch order chosen so the big GEMM is the 4th launch (the ncu-profiled slot).
    detect_mask_kernel<<<1, 256>>>((const unsigned int*)mask);          // 1
    conv_f16_kernel<<<32000, 256>>>(emb, af16, 8192000);                // 2
    wtrans_kernel<<<3072, 256>>>(Wkvl, wkt, 1536);                      // 3

    // kvl = embeddings @ W_kvl  [64000 x 1536] -> fp16                 // 4 (profiled)
    {
        dim3 grid(6, 500);
        hmma_gemm_big<<<grid, 256, 147456>>>(af16, wkt, kvlhp, 1536);
    }

    wtrans_kernel<<<1024, 256>>>(Wout, wot, 512);                       // 5

    // attention
    {
        dim3 grid(8, 64);
        attn_kernel<<<grid, 640>>>(q, mask);                            // 6
    }

    // glimpse = heads @ W_out  [1280 x 512] fp16 -> fp32
    conv_f16_kernel<<<640, 256>>>(headsp, hf16, 163840);                // 7
    {
        dim3 grid(4, 10);
        hmma_gemm<<<grid, 256, 65536>>>(hf16, wot, glimpsep, 512);      // 8
    }

    // pointer logits
    {
        dim3 grid(64, 2, 5);
        pointer_kernel<<<grid, 256>>>(mask);                            // 9
    }

    // log-softmax
    {
        dim3 grid(20, 64);
        lsm_kernel<<<grid, 256>>>(out);                                 // 10
    }
}

// round 7
// speedup vs baseline: 1.4651x; 1.0866x over previous
#include <cuda_runtime.h>
#include <cuda_fp16.h>
#include <cstdint>

// B=64, N=1000, D=512, H=8, S=20, DK=64
#define NEG_BIG (-1e9f)
#define INV_SQRT_DK 0.125f
#define INV_SQRT_D 0.04419417382415922f

// ---------------- device scratch ----------------
__device__ __align__(16) __half g_kvlh[64000 * 1536];    // fp16 [b*1000+n][gk|gv|lk]
__device__ __align__(16) float g_heads[1280 * 512];
__device__ __align__(16) float g_glimpse[1280 * 512];
__device__ __align__(16) float g_logits[1280 * 1000];
__device__ __align__(16) __half g_Af16[64000 * 512];
__device__ __align__(16) __half g_Wkvl_t[1536 * 512];
__device__ __align__(16) __half g_Wout_t[512 * 512];
__device__ __align__(16) __half g_Hf16[1280 * 512];
__device__ __align__(16) unsigned int g_mbits[1280 * 32]; // packed feasibility bits

// ---------------- helpers ----------------
__device__ __forceinline__ float warp_max(float v) {
#pragma unroll
    for (int o = 16; o; o >>= 1) v = fmaxf(v, __shfl_xor_sync(0xffffffffu, v, o));
    return v;
}
__device__ __forceinline__ float warp_sum(float v) {
#pragma unroll
    for (int o = 16; o; o >>= 1) v += __shfl_xor_sync(0xffffffffu, v, o);
    return v;
}
__device__ __forceinline__ uint32_t smem_u32(const void* p) {
    uint32_t a;
    asm("{ .reg .u64 t; cvta.to.shared.u64 t, %1; cvt.u32.u64 %0, t; }" : "=r"(a) : "l"(p));
    return a;
}
__device__ __forceinline__ void cp_async16(uint32_t saddr, const void* gaddr) {
    asm volatile("cp.async.cg.shared.global [%0], [%1], 16;" :: "r"(saddr), "l"(gaddr));
}
__device__ __forceinline__ void cp_commit() { asm volatile("cp.async.commit_group;" ::: "memory"); }
__device__ __forceinline__ void cp_wait1() { asm volatile("cp.async.wait_group 1;" ::: "memory"); }
__device__ __forceinline__ void cp_wait0() { asm volatile("cp.async.wait_group 0;" ::: "memory"); }

__device__ __forceinline__ void ldsm_x4(uint32_t& r0, uint32_t& r1, uint32_t& r2, uint32_t& r3,
                                        uint32_t addr) {
    asm volatile("ldmatrix.sync.aligned.m8n8.x4.shared.b16 {%0,%1,%2,%3}, [%4];"
                 : "=r"(r0), "=r"(r1), "=r"(r2), "=r"(r3) : "r"(addr));
}
__device__ __forceinline__ void mma16816(float& c0, float& c1, float& c2, float& c3,
                                         uint32_t a0, uint32_t a1, uint32_t a2, uint32_t a3,
                                         uint32_t b0, uint32_t b1) {
    asm volatile(
        "mma.sync.aligned.m16n8k16.row.col.f32.f16.f16.f32 "
        "{%0,%1,%2,%3}, {%4,%5,%6,%7}, {%8,%9}, {%0,%1,%2,%3};"
        : "+f"(c0), "+f"(c1), "+f"(c2), "+f"(c3)
        : "r"(a0), "r"(a1), "r"(a2), "r"(a3), "r"(b0), "r"(b1));
}

// ---------------- mask -> packed bits (self-detecting dtype) ----------------
// grid 1280 (one block per (b,s) row), 256 threads.
__global__ __launch_bounds__(256)
void mask_bits_kernel(const unsigned int* __restrict__ mw)
{
    __shared__ int flags;
    if (threadIdx.x == 0) flags = 0;
    __syncthreads();
    int f = 0;
    for (int i = threadIdx.x; i < 1024; i += 256) {
        unsigned int v = mw[i];
        if (v != 0u && v != 1u) f |= 1;
        if (v != 0u && v != 0x3F800000u) f |= 2;
    }
    if (f) atomicOr(&flags, f);
    __syncthreads();
    const int mode = ((flags & 1) && (flags & 2)) ? 0 : 1;  // 0=bytes, 1=words

    const int lane = threadIdx.x & 31, wid = threadIdx.x >> 5;
    const int row = blockIdx.x;
#pragma unroll
    for (int j = 0; j < 4; j++) {
        int widx = wid * 4 + j;
        int n = widx * 32 + lane;
        bool feas = false;
        if (n < 1000) {
            int idx = row * 1000 + n;
            feas = mode ? (mw[idx] != 0u)
                        : (((const unsigned char*)mw)[idx] != 0);
        }
        unsigned int word = __ballot_sync(0xffffffffu, feas);
        if (lane == 0) g_mbits[row * 32 + widx] = word;
    }
}

// ---------------- fused prep: conv emb->fp16, wtrans Wkvl, wtrans Wout ----------------
// grid 36096: [0,32000) conv emb; [32000,35072) Wkvl^T; [35072,36096) Wout^T
__global__ __launch_bounds__(256)
void prep_kernel(const float* __restrict__ emb, const float* __restrict__ Wkvl,
                 const float* __restrict__ Wout)
{
    int bid = blockIdx.x;
    int tid = threadIdx.x;
    if (bid < 32000) {
        int i = bid * 256 + tid;             // < 8192000
        float4 v = ((const float4*)emb)[i];
        ((__half2*)g_Af16)[i * 2] = __floats2half2_rn(v.x, v.y);
        ((__half2*)g_Af16)[i * 2 + 1] = __floats2half2_rn(v.z, v.w);
    } else if (bid < 35072) {
        int idx = (bid - 32000) * 256 + tid; // < 1536*512
        int n = idx >> 9, k = idx & 511;
        g_Wkvl_t[idx] = __float2half_rn(Wkvl[(size_t)k * 1536 + n]);
    } else {
        int idx = (bid - 35072) * 256 + tid; // < 512*512
        int n = idx >> 9, k = idx & 511;
        g_Wout_t[idx] = __float2half_rn(Wout[(size_t)k * 512 + n]);
    }
}

// ---------------- fp32 -> fp16 (heads) ----------------
__global__ __launch_bounds__(256)
void conv_f16_kernel(const float* __restrict__ x, __half* __restrict__ y, int n4)
{
    int i = blockIdx.x * 256 + threadIdx.x;
    if (i >= n4) return;
    float4 v = ((const float4*)x)[i];
    ((__half2*)y)[i * 2] = __floats2half2_rn(v.x, v.y);
    ((__half2*)y)[i * 2 + 1] = __floats2half2_rn(v.z, v.w);
}

// ---------------- BIG fp16 HMMA GEMM: 128x256 tile, 8 warps ----------------
__global__ __launch_bounds__(256)
void hmma_gemm_big(const __half* __restrict__ A, const __half* __restrict__ Bt,
                   __half* __restrict__ C, int Nn)
{
    extern __shared__ char dsm[];
    const uint32_t sb = smem_u32(dsm);
    const int tid = threadIdx.x;
    const int bm = blockIdx.y * 128;
    const int bn = blockIdx.x * 256;
    const int lane = tid & 31, w = tid >> 5;
    const int wr = w >> 2;
    const int wc = w & 3;

    const char* Ag = (const char*)A + (size_t)bm * 1024;
    const char* Bg = (const char*)Bt + (size_t)bn * 1024;

#define LOAD_CHUNK(kc)                                                      \
    do {                                                                    \
        uint32_t st_ = sb + ((kc) % 3) * 49152;                             \
        size_t gk_ = (size_t)(kc) * 128;                                    \
        _Pragma("unroll")                                                   \
        for (int i_ = 0; i_ < 4; i_++) {                                    \
            int g_ = tid + i_ * 256;                                        \
            int row_ = g_ >> 3, ch_ = g_ & 7;                               \
            uint32_t off_ = row_ * 128 + ch_ * 16;                          \
            uint32_t sw_ = off_ ^ ((off_ >> 3) & 0x70);                     \
            cp_async16(st_ + sw_, Ag + (size_t)row_ * 1024 + gk_ + ch_ * 16); \
        }                                                                   \
        _Pragma("unroll")                                                   \
        for (int i_ = 0; i_ < 8; i_++) {                                    \
            int g_ = tid + i_ * 256;                                        \
            int row_ = g_ >> 3, ch_ = g_ & 7;                               \
            uint32_t off_ = row_ * 128 + ch_ * 16;                          \
            uint32_t sw_ = off_ ^ ((off_ >> 3) & 0x70);                     \
            cp_async16(st_ + 16384 + sw_, Bg + (size_t)row_ * 1024 + gk_ + ch_ * 16); \
        }                                                                   \
        cp_commit();                                                        \
    } while (0)

    float acc[4][8][4];
#pragma unroll
    for (int i = 0; i < 4; i++)
#pragma unroll
        for (int j = 0; j < 8; j++)
#pragma unroll
            for (int r = 0; r < 4; r++) acc[i][j][r] = 0.f;

    LOAD_CHUNK(0);
    LOAD_CHUNK(1);

    const int a_row = (lane & 15);
    const int a_c16 = (lane >> 4);
    const int b_nrow = (lane & 7) + ((lane >> 4) & 1) * 8;
    const int b_c16 = (lane >> 3) & 1;

    for (int kc = 0; kc < 8; ++kc) {
        if (kc == 7) cp_wait0(); else cp_wait1();
        __syncthreads();
        if (kc + 2 < 8) LOAD_CHUNK(kc + 2);

        uint32_t st = sb + (kc % 3) * 49152;
#pragma unroll
        for (int ks = 0; ks < 4; ++ks) {
            uint32_t af[4][4];
#pragma unroll
            for (int mi = 0; mi < 4; ++mi) {
                uint32_t off = (uint32_t)(wr * 64 + mi * 16 + a_row) * 128 + ks * 32 + a_c16 * 16;
                uint32_t sw = off ^ ((off >> 3) & 0x70);
                ldsm_x4(af[mi][0], af[mi][1], af[mi][2], af[mi][3], st + sw);
            }
            uint32_t bf[4][4];
#pragma unroll
            for (int pr = 0; pr < 4; ++pr) {
                uint32_t off = (uint32_t)(wc * 64 + pr * 16 + b_nrow) * 128 + ks * 32 + b_c16 * 16;
                uint32_t sw = off ^ ((off >> 3) & 0x70);
                ldsm_x4(bf[pr][0], bf[pr][1], bf[pr][2], bf[pr][3], st + 16384 + sw);
            }
#pragma unroll
            for (int mi = 0; mi < 4; ++mi) {
#pragma unroll
                for (int pr = 0; pr < 4; ++pr) {
                    mma16816(acc[mi][pr * 2][0], acc[mi][pr * 2][1],
                             acc[mi][pr * 2][2], acc[mi][pr * 2][3],
                             af[mi][0], af[mi][1], af[mi][2], af[mi][3],
                             bf[pr][0], bf[pr][1]);
                    mma16816(acc[mi][pr * 2 + 1][0], acc[mi][pr * 2 + 1][1],
                             acc[mi][pr * 2 + 1][2], acc[mi][pr * 2 + 1][3],
                             af[mi][0], af[mi][1], af[mi][2], af[mi][3],
                             bf[pr][2], bf[pr][3]);
                }
            }
        }
    }
    __syncthreads();

#pragma unroll
    for (int mi = 0; mi < 4; ++mi) {
        int row0 = bm + wr * 64 + mi * 16 + (lane >> 2);
#pragma unroll
        for (int ni = 0; ni < 8; ++ni) {
            int col = bn + wc * 64 + ni * 8 + (lane & 3) * 2;
            *(__half2*)(C + (size_t)row0 * Nn + col) =
                __floats2half2_rn(acc[mi][ni][0], acc[mi][ni][1]);
            *(__half2*)(C + (size_t)(row0 + 8) * Nn + col) =
                __floats2half2_rn(acc[mi][ni][2], acc[mi][ni][3]);
        }
    }
#undef LOAD_CHUNK
}

// ---------------- small fp16 HMMA GEMM (glimpse): 128x128, fp32 out ----------------
__global__ __launch_bounds__(256, 2)
void hmma_gemm(const __half* __restrict__ A, const __half* __restrict__ Bt,
               float* __restrict__ C, int Nn)
{
    extern __shared__ char dsm[];
    const uint32_t sb = smem_u32(dsm);
    const int tid = threadIdx.x;
    const int bm = blockIdx.y * 128;
    const int bn = blockIdx.x * 128;
    const int lane = tid & 31, w = tid >> 5;
    const int wr = w >> 2;
    const int wc = w & 3;

    const char* Ag = (const char*)A + (size_t)bm * 1024;
    const char* Bg = (const char*)Bt + (size_t)bn * 1024;

#define LOAD_CHUNK(kc)                                                      \
    do {                                                                    \
        uint32_t st_ = sb + ((kc) & 1) * 32768;                             \
        size_t gk_ = (size_t)(kc) * 128;                                    \
        _Pragma("unroll")                                                   \
        for (int i_ = 0; i_ < 4; i_++) {                                    \
            int g_ = tid + i_ * 256;                                        \
            int row_ = g_ >> 3, ch_ = g_ & 7;                               \
            uint32_t off_ = row_ * 128 + ch_ * 16;                          \
            uint32_t sw_ = off_ ^ ((off_ >> 3) & 0x70);                     \
            size_t go_ = (size_t)row_ * 1024 + gk_ + ch_ * 16;              \
            cp_async16(st_ + sw_, Ag + go_);                                \
            cp_async16(st_ + 16384 + sw_, Bg + go_);                        \
        }                                                                   \
        cp_commit();                                                        \
    } while (0)

    float acc[4][4][4];
#pragma unroll
    for (int i = 0; i < 4; i++)
#pragma unroll
        for (int j = 0; j < 4; j++)
#pragma unroll
            for (int r = 0; r < 4; r++) acc[i][j][r] = 0.f;

    LOAD_CHUNK(0);

    const int a_row = (lane & 15);
    const int a_c16 = (lane >> 4);
    const int b_nrow = (lane & 7) + ((lane >> 4) & 1) * 8;
    const int b_c16 = (lane >> 3) & 1;

    for (int kc = 0; kc < 8; ++kc) {
        if (kc + 1 < 8) { LOAD_CHUNK(kc + 1); cp_wait1(); } else { cp_wait0(); }
        __syncthreads();

        uint32_t st = sb + (kc & 1) * 32768;
#pragma unroll
        for (int ks = 0; ks < 4; ++ks) {
            uint32_t af[4][4];
#pragma unroll
            for (int mi = 0; mi < 4; ++mi) {
                uint32_t off = (uint32_t)(wr * 64 + mi * 16 + a_row) * 128 + ks * 32 + a_c16 * 16;
                uint32_t sw = off ^ ((off >> 3) & 0x70);
                ldsm_x4(af[mi][0], af[mi][1], af[mi][2], af[mi][3], st + sw);
            }
            uint32_t bf[2][4];
#pragma unroll
            for (int pr = 0; pr < 2; ++pr) {
                uint32_t off = (uint32_t)(wc * 32 + pr * 16 + b_nrow) * 128 + ks * 32 + b_c16 * 16;
                uint32_t sw = off ^ ((off >> 3) & 0x70);
                ldsm_x4(bf[pr][0], bf[pr][1], bf[pr][2], bf[pr][3], st + 16384 + sw);
            }
#pragma unroll
            for (int mi = 0; mi < 4; ++mi) {
#pragma unroll
                for (int pr = 0; pr < 2; ++pr) {
                    mma16816(acc[mi][pr * 2][0], acc[mi][pr * 2][1],
                             acc[mi][pr * 2][2], acc[mi][pr * 2][3],
                             af[mi][0], af[mi][1], af[mi][2], af[mi][3],
                             bf[pr][0], bf[pr][1]);
                    mma16816(acc[mi][pr * 2 + 1][0], acc[mi][pr * 2 + 1][1],
                             acc[mi][pr * 2 + 1][2], acc[mi][pr * 2 + 1][3],
                             af[mi][0], af[mi][1], af[mi][2], af[mi][3],
                             bf[pr][2], bf[pr][3]);
                }
            }
        }
        __syncthreads();
    }

#pragma unroll
    for (int mi = 0; mi < 4; ++mi) {
        int row0 = bm + wr * 64 + mi * 16 + (lane >> 2);
#pragma unroll
        for (int ni = 0; ni < 4; ++ni) {
            int col = bn + wc * 32 + ni * 8 + (lane & 3) * 2;
            *(float2*)(C + (size_t)row0 * Nn + col) = make_float2(acc[mi][ni][0], acc[mi][ni][1]);
            *(float2*)(C + (size_t)(row0 + 8) * Nn + col) = make_float2(acc[mi][ni][2], acc[mi][ni][3]);
        }
    }
#undef LOAD_CHUNK
}

// ---------------- flash-style masked MHA with register-resident mask bits ----------------
__global__ __launch_bounds__(640)
void attn_kernel(const float* __restrict__ qin)
{
    __shared__ __align__(16) float sq[20][64];
    __shared__ __align__(16) float sk[40][64];
    __shared__ __align__(16) float sv[40][64];
    const int h = blockIdx.x, b = blockIdx.y;
    const int tid = threadIdx.x;

    if (tid < 320) {
        int s = tid >> 4, dg = (tid & 15) << 2;
        *(float4*)&sq[s][dg] = *(const float4*)(qin + (size_t)(b * 20 + s) * 512 + h * 64 + dg);
    }

    const int lane = tid & 31, w = tid >> 5;
    float m = -1e30f, l = 0.f, acc0 = 0.f, acc1 = 0.f;
    float q0 = 0.f, q1 = 0.f;
    unsigned int mword = 0;
    if (w < 20) mword = g_mbits[(b * 20 + w) * 32 + lane];   // lane l holds word l

    const int nn = tid >> 4;
    const int dg = (tid & 15) << 2;

    for (int t = 0; t < 25; ++t) {
        const int n0 = t * 40;
        __syncthreads();
        {
            const __half* base = g_kvlh + (size_t)(b * 1000 + n0 + nn) * 1536 + h * 64 + dg;
            __half2 k01 = *(const __half2*)(base);
            __half2 k23 = *(const __half2*)(base + 2);
            __half2 v01 = *(const __half2*)(base + 512);
            __half2 v23 = *(const __half2*)(base + 514);
            float2 kf0 = __half22float2(k01), kf1 = __half22float2(k23);
            float2 vf0 = __half22float2(v01), vf1 = __half22float2(v23);
            *(float4*)&sk[nn][dg] = make_float4(kf0.x, kf0.y, kf1.x, kf1.y);
            *(float4*)&sv[nn][dg] = make_float4(vf0.x, vf0.y, vf1.x, vf1.y);
        }
        __syncthreads();
        if (w < 20) {
            if (t == 0) { q0 = sq[w][lane]; q1 = sq[w][lane + 32]; }
#pragma unroll 4
            for (int n = 0; n < 40; ++n) {
                const int gn = n0 + n;
                unsigned int wd = __shfl_sync(0xffffffffu, mword, gn >> 5);
                if ((wd >> (gn & 31)) & 1u) {        // warp-uniform branch, no memory dep
                    float x = q0 * sk[n][lane] + q1 * sk[n][lane + 32];
                    x += __shfl_xor_sync(0xffffffffu, x, 16);
                    x += __shfl_xor_sync(0xffffffffu, x, 8);
                    x += __shfl_xor_sync(0xffffffffu, x, 4);
                    x += __shfl_xor_sync(0xffffffffu, x, 2);
                    x += __shfl_xor_sync(0xffffffffu, x, 1);
                    x *= INV_SQRT_DK;
                    float mn = fmaxf(m, x);
                    float corr = __expf(m - mn);
                    float p = __expf(x - mn);
                    l = l * corr + p;
                    acc0 = acc0 * corr + p * sv[n][lane];
                    acc1 = acc1 * corr + p * sv[n][lane + 32];
                    m = mn;
                }
            }
        }
    }
    if (w < 20) {
        float inv = 1.f / l;
        size_t o = (size_t)(b * 20 + w) * 512 + h * 64 + lane;
        g_heads[o] = acc0 * inv;
        g_heads[o + 32] = acc1 * inv;
    }
}

// ---------------- pointer logits (bitmask, hoisted load) ----------------
__global__ __launch_bounds__(256)
void pointer_kernel()
{
    __shared__ __align__(16) float sg[10 * 512];
    __shared__ __align__(16) float slk[8 * 512];
    const int b = blockIdx.x;
    const int sbase = blockIdx.y * 10;
    const int nsl = blockIdx.z;
    const int tid = threadIdx.x;

    for (int i = tid; i < 10 * 512 / 4; i += 256) {
        int off = i << 2;
        int s = off >> 9, d = off & 511;
        *(float4*)&sg[off] = *(const float4*)(g_glimpse + (size_t)(b * 20 + sbase + s) * 512 + d);
    }

    const int lane = tid & 31, w = tid >> 5;
    for (int t = 0; t < 25; ++t) {
        const int n0 = nsl * 200 + t * 8;
        __syncthreads();
        for (int i = tid; i < 8 * 512 / 8; i += 256) {
            int off = i << 3;
            int nn = off >> 9, d = off & 511;
            const __half* src = g_kvlh + (size_t)(b * 1000 + n0 + nn) * 1536 + 1024 + d;
            uint4 raw = *(const uint4*)src;
            const __half2* hp = (const __half2*)&raw;
            float2 f0 = __half22float2(hp[0]);
            float2 f1 = __half22float2(hp[1]);
            float2 f2 = __half22float2(hp[2]);
            float2 f3 = __half22float2(hp[3]);
            *(float4*)&slk[off] = make_float4(f0.x, f0.y, f1.x, f1.y);
            *(float4*)&slk[off + 4] = make_float4(f2.x, f2.y, f3.x, f3.y);
        }
        __syncthreads();
#pragma unroll
        for (int pp = 0; pp < 10; ++pp) {
            const int p = w * 10 + pp;
            const int sl = p >> 3, n = p & 7;
            const int gn = n0 + n;
            unsigned int wd = 0;
            if (lane == 0)                         // issued before the dot -> latency hidden
                wd = g_mbits[(b * 20 + sbase + sl) * 32 + (gn >> 5)];
            const float* gr = &sg[sl * 512];
            const float* kr = &slk[n * 512];
            float sum = 0.f;
#pragma unroll
            for (int i = 0; i < 16; ++i)
                sum += gr[lane + i * 32] * kr[lane + i * 32];
            sum = warp_sum(sum);
            if (lane == 0) {
                float lg = ((wd >> (gn & 31)) & 1u)
                         ? 10.f * tanhf(sum * INV_SQRT_D) : NEG_BIG;
                g_logits[(b * 20 + sbase + sl) * 1000 + gn] = lg;
            }
        }
    }
}

// ---------------- log-softmax + transposed writeout ----------------
__global__ __launch_bounds__(256)
void lsm_kernel(float* __restrict__ out)
{
    const int s = blockIdx.x, b = blockIdx.y;
    const float* row = g_logits + (size_t)(b * 20 + s) * 1000;
    float* orow = out + (size_t)(s * 64 + b) * 1000;
    __shared__ float red[8];
    const int tid = threadIdx.x;
    const int lane = tid & 31, w = tid >> 5;

    float mx = -1e30f;
    for (int i = tid; i < 1000; i += 256) mx = fmaxf(mx, row[i]);
    mx = warp_max(mx);
    if (lane == 0) red[w] = mx;
    __syncthreads();
    if (w == 0) {
        float v = (lane < 8) ? red[lane] : -1e30f;
        v = warp_max(v);
        if (lane == 0) red[0] = v;
    }
    __syncthreads();
    mx = red[0];
    __syncthreads();

    float se = 0.f;
    for (int i = tid; i < 1000; i += 256) se += __expf(row[i] - mx);
    se = warp_sum(se);
    if (lane == 0) red[w] = se;
    __syncthreads();
    if (w == 0) {
        float v = (lane < 8) ? red[lane] : 0.f;
        v = warp_sum(v);
        if (lane == 0) red[0] = v;
    }
    __syncthreads();
    const float lse = mx + logf(red[0]);

    for (int i = tid; i < 1000; i += 256) orow[i] = row[i] - lse;
}

// ---------------- launch ----------------
extern "C" void kernel_launch(void* const* d_in, const int* in_sizes, int n_in,
                              void* d_out, int out_size)
{
    (void)out_size;
    const float* emb = nullptr;
    const float* q = nullptr;
    const void* mask = nullptr;
    const float* Wkvl = nullptr;
    const float* Wout = nullptr;
    for (int i = 0; i < n_in; ++i) {
        switch (in_sizes[i]) {
            case 32768000: emb = (const float*)d_in[i]; break;
            case 655360:   q = (const float*)d_in[i]; break;
            case 1280000:  mask = d_in[i]; break;
            case 786432:   Wkvl = (const float*)d_in[i]; break;
            case 262144:   Wout = (const float*)d_in[i]; break;
            default: break;
        }
    }
    float* out = (float*)d_out;

    float *headsp, *glimpsep;
    __half *kvlhp, *af16, *wkt, *wot, *hf16;
    cudaGetSymbolAddress((void**)&kvlhp, g_kvlh);
    cudaGetSymbolAddress((void**)&headsp, g_heads);
    cudaGetSymbolAddress((void**)&glimpsep, g_glimpse);
    cudaGetSymbolAddress((void**)&af16, g_Af16);
    cudaGetSymbolAddress((void**)&wkt, g_Wkvl_t);
    cudaGetSymbolAddress((void**)&wot, g_Wout_t);
    cudaGetSymbolAddress((void**)&hf16, g_Hf16);

    cudaFuncSetAttribute(hmma_gemm_big, cudaFuncAttributeMaxDynamicSharedMemorySize, 147456);
    cudaFuncSetAttribute(hmma_gemm, cudaFuncAttributeMaxDynamicSharedMemorySize, 65536);

    mask_bits_kernel<<<1280, 256>>>((const unsigned int*)mask);         // 1
    prep_kernel<<<36096, 256>>>(emb, Wkvl, Wout);                       // 2

    // kvl = embeddings @ W_kvl  [64000 x 1536] -> fp16                 // 3
    {
        dim3 grid(6, 500);
        hmma_gemm_big<<<grid, 256, 147456>>>(af16, wkt, kvlhp, 1536);
    }

    // attention                                                        // 4 (profiled)
    {
        dim3 grid(8, 64);
        attn_kernel<<<grid, 640>>>(q);
    }

    // glimpse = heads @ W_out  [1280 x 512] fp16 -> fp32
    conv_f16_kernel<<<640, 256>>>(headsp, hf16, 163840);                // 5
    {
        dim3 grid(4, 10);
        hmma_gemm<<<grid, 256, 65536>>>(hf16, wot, glimpsep, 512);      // 6
    }

    // pointer logits
    {
        dim3 grid(64, 2, 5);
        pointer_kernel<<<grid, 256>>>();                                // 7
    }

    // log-softmax
    {
        dim3 grid(20, 64);
        lsm_kernel<<<grid, 256>>>(out);                                 // 8
    }
}